// round 4
// baseline (speedup 1.0000x reference)
#include <cuda_runtime.h>
#include <cuda_bf16.h>
#include <math.h>
#include <stdint.h>

#define T_TOK   4096
#define D_MODEL 2048
#define FF      8192
#define NE      8
#define PM      48          // padded 128-row blocks (256-aligned per expert)
#define MAXTILE 24          // max 256-row tiles
#define KT1     32          // GEMM1 k-tiles (D/64)
#define NT1     64          // GEMM1 n-tiles (FF/128)
#define KT2     128         // GEMM2 k-tiles (FF/64)
#define NT2     16          // GEMM2 n-tiles (D/128)
#define BLKB    32768       // one operand block: hi 16KB + lo 16KB (128 rows x 128B)

// ---------------- scratch ----------------
__device__ int   g_idx[T_TOK];
__device__ float g_w[T_TOK];
__device__ int   g_order[T_TOK];
__device__ int   g_off[NE + 1];
__device__ int   g_ptok[PM * 128];
__device__ int   g_tile_e[MAXTILE];
__device__ int   g_tile_gt[MAXTILE];
__device__ int   g_ntiles;

__device__ __align__(128) char g_A [(size_t)PM * KT1 * BLKB];
__device__ __align__(128) char g_B1[(size_t)NE * NT1 * KT1 * BLKB];
__device__ __align__(128) char g_B2[(size_t)NE * NT2 * KT2 * BLKB];
__device__ __align__(128) char g_H [(size_t)PM * KT2 * BLKB];

// ---------------- helpers ----------------
__device__ __forceinline__ uint32_t s2u(const void* p) {
    uint32_t a;
    asm("{ .reg .u64 t; cvta.to.shared.u64 t, %1; cvt.u32.u64 %0, t; }" : "=r"(a) : "l"(p));
    return a;
}
__device__ __forceinline__ uint32_t pack2(float a, float b) {
    __nv_bfloat162 t = __floats2bfloat162_rn(a, b);
    return *(uint32_t*)&t;
}
__device__ __forceinline__ void split1(float v, float& hi, float& lo) {
    __nv_bfloat16 h = __float2bfloat16_rn(v);
    hi = __bfloat162float(h);
    lo = v - hi;
}
__device__ __forceinline__ float gelu_exact(float v) {
    return 0.5f * v * (1.0f + erff(v * 0.70710678118654752440f));
}
__device__ __forceinline__ void mbar_init(uint32_t m, uint32_t c) {
    asm volatile("mbarrier.init.shared::cta.b64 [%0], %1;" :: "r"(m), "r"(c) : "memory");
}
__device__ __forceinline__ void mbar_arrive(uint32_t m) {
    asm volatile("mbarrier.arrive.shared::cta.b64 _, [%0];" :: "r"(m) : "memory");
}
__device__ __forceinline__ void mbar_expect_tx(uint32_t m, uint32_t b) {
    asm volatile("mbarrier.arrive.expect_tx.shared::cta.b64 _, [%0], %1;"
                 :: "r"(m), "r"(b) : "memory");
}
__device__ __forceinline__ void mbar_wait(uint32_t m, uint32_t ph) {
    asm volatile(
        "{\n\t.reg .pred P;\n"
        "W_%=:\n\t"
        "mbarrier.try_wait.parity.acquire.cta.shared::cta.b64 P, [%0], %1, 0x989680;\n\t"
        "@P bra.uni D_%=;\n\t"
        "bra.uni W_%=;\n"
        "D_%=:\n\t}"
        :: "r"(m), "r"(ph) : "memory");
}
__device__ __forceinline__ void bulk_g2s(uint32_t dst, const void* src, uint32_t bytes,
                                         uint32_t mbar) {
    asm volatile(
        "cp.async.bulk.shared::cta.global.mbarrier::complete_tx::bytes [%0], [%1], %2, [%3];"
        :: "r"(dst), "l"(src), "r"(bytes), "r"(mbar) : "memory");
}
__device__ __forceinline__ void ldsm4(uint32_t& r0, uint32_t& r1, uint32_t& r2, uint32_t& r3,
                                      uint32_t a) {
    asm volatile("ldmatrix.sync.aligned.m8n8.x4.shared.b16 {%0,%1,%2,%3}, [%4];"
                 : "=r"(r0), "=r"(r1), "=r"(r2), "=r"(r3) : "r"(a));
}
__device__ __forceinline__ void mma_bf16(float* d, const uint32_t* a, const uint32_t* b) {
    asm volatile(
        "mma.sync.aligned.m16n8k16.row.col.f32.bf16.bf16.f32 "
        "{%0,%1,%2,%3}, {%4,%5,%6,%7}, {%8,%9}, {%0,%1,%2,%3};"
        : "+f"(d[0]), "+f"(d[1]), "+f"(d[2]), "+f"(d[3])
        : "r"(a[0]), "r"(a[1]), "r"(a[2]), "r"(a[3]), "r"(b[0]), "r"(b[1]));
}

// ---------------- router ----------------
__global__ void router_kernel(const float* __restrict__ x, const float* __restrict__ Wr) {
    __shared__ float sx[D_MODEL];
    __shared__ float slog[NE];
    const int t = blockIdx.x, tid = threadIdx.x;
    const float* xr = x + (size_t)t * D_MODEL;
    for (int i = tid * 4; i < D_MODEL; i += 256 * 4)
        *(float4*)(sx + i) = *(const float4*)(xr + i);
    __syncthreads();
    const int w = tid >> 5, lane = tid & 31;
    const float* wr = Wr + (size_t)w * D_MODEL;
    float s = 0.f;
    for (int i = lane; i < D_MODEL; i += 32) s += sx[i] * wr[i];
    #pragma unroll
    for (int o = 16; o; o >>= 1) s += __shfl_xor_sync(0xffffffffu, s, o);
    if (lane == 0) slog[w] = s;
    __syncthreads();
    if (tid == 0) {
        float mx = slog[0]; int mi = 0;
        #pragma unroll
        for (int e = 1; e < NE; e++) if (slog[e] > mx) { mx = slog[e]; mi = e; }
        float sum = 0.f;
        #pragma unroll
        for (int e = 0; e < NE; e++) sum += expf(slog[e] - mx);
        g_idx[t] = mi;
        g_w[t] = 1.0f / sum;
    }
}

// ---------------- bucket: counts, offsets (256-pad), tile table, padded token map ----
__global__ void bucket_kernel() {
    __shared__ int cnt[NE], off[NE], soff[NE], spo[NE + 1];
    const int tid = threadIdx.x;
    if (tid < NE) cnt[tid] = 0;
    __syncthreads();
    for (int t = tid; t < T_TOK; t += blockDim.x) atomicAdd(&cnt[g_idx[t]], 1);
    __syncthreads();
    if (tid == 0) {
        int acc = 0, pacc = 0, nt = 0;
        #pragma unroll
        for (int e = 0; e < NE; e++) {
            off[e] = acc; soff[e] = acc; g_off[e] = acc;
            spo[e] = pacc;
            int tiles = (cnt[e] + 255) >> 8;
            for (int i = 0; i < tiles; i++) {
                g_tile_e[nt] = e;
                g_tile_gt[nt] = (pacc >> 8) + i;
                nt++;
            }
            acc += cnt[e];
            pacc += tiles << 8;
        }
        g_off[NE] = acc;
        spo[NE] = pacc;
        g_ntiles = nt;
    }
    __syncthreads();
    for (int t = tid; t < T_TOK; t += blockDim.x) {
        int p = atomicAdd(&off[g_idx[t]], 1);
        g_order[p] = t;
    }
    __syncthreads();
    for (int p = tid; p < PM * 128; p += blockDim.x) {
        int tk = -1;
        #pragma unroll
        for (int e = 0; e < NE; e++)
            if (p >= spo[e] && p < spo[e] + cnt[e])
                tk = g_order[soff[e] + (p - spo[e])];
        g_ptok[p] = tk;
    }
}

// ---------------- prepass: gather x rows -> swizzled bf16 hi/lo blocks ----------------
__global__ void __launch_bounds__(256) gather_a_kernel(const float* __restrict__ x) {
    const int gt = blockIdx.x, kt = blockIdx.y;
    const int tid = threadIdx.x;
    const int r = tid >> 1, half = tid & 1;
    const int tok = g_ptok[gt * 128 + r];
    uint32_t hw[16], lw[16];
    if (tok >= 0) {
        const float4* src = (const float4*)(x + (size_t)tok * D_MODEL + kt * 64 + half * 32);
        #pragma unroll
        for (int q = 0; q < 8; q++) {
            float4 v = src[q];
            float h0, l0, h1, l1, h2, l2, h3, l3;
            split1(v.x, h0, l0); split1(v.y, h1, l1);
            split1(v.z, h2, l2); split1(v.w, h3, l3);
            hw[q * 2]     = pack2(h0, h1); hw[q * 2 + 1] = pack2(h2, h3);
            lw[q * 2]     = pack2(l0, l1); lw[q * 2 + 1] = pack2(l2, l3);
        }
    } else {
        #pragma unroll
        for (int q = 0; q < 16; q++) { hw[q] = 0; lw[q] = 0; }
    }
    char* blk = g_A + ((size_t)gt * KT1 + kt) * BLKB;
    #pragma unroll
    for (int c = 0; c < 4; c++) {
        int ch = half * 4 + c;
        uint32_t off = (uint32_t)(r * 128) + (uint32_t)((ch ^ (r & 7)) << 4);
        *(uint4*)(blk + off)         = ((uint4*)hw)[c];
        *(uint4*)(blk + 16384 + off) = ((uint4*)lw)[c];
    }
}

// ---------------- prepass: transpose + convert weights (128x128 tile) ----------------
// W=1: src [E][D][F] -> g_B1 blocks; W=2: src [E][F][D] -> g_B2 blocks
template <int W>
__global__ void __launch_bounds__(512) transconv_kernel(const float* __restrict__ src) {
    constexpr int Cn = (W == 1) ? FF : D_MODEL;
    constexpr int Rk = (W == 1) ? D_MODEL : FF;
    constexpr int NT = (W == 1) ? NT1 : NT2;
    constexpr int KT = (W == 1) ? KT1 : KT2;
    extern __shared__ float s[];              // 128 x 132
    const int nt = blockIdx.x, yk = blockIdx.y, e = blockIdx.z;
    const int tid = threadIdx.x;
    const float* sp = src + (size_t)e * Rk * Cn + (size_t)(yk * 128) * Cn + nt * 128;
    #pragma unroll
    for (int i = 0; i < 8; i++) {
        int q = i * 512 + tid;
        int k = q >> 5, c4 = q & 31;
        *(float4*)(s + k * 132 + c4 * 4) = *(const float4*)(sp + (size_t)k * Cn + c4 * 4);
    }
    __syncthreads();
    const int w = tid >> 5, lane = tid & 31;
    const int n = (w & 3) * 32 + lane;
    const int sub = (w >> 3) & 1, half = (w >> 2) & 1;
    const int k0 = sub * 64 + half * 32;
    uint32_t hw[16], lw[16];
    #pragma unroll
    for (int jw = 0; jw < 16; jw++) {
        float v0 = s[(k0 + jw * 2) * 132 + n];
        float v1 = s[(k0 + jw * 2 + 1) * 132 + n];
        float h0, l0, h1, l1;
        split1(v0, h0, l0); split1(v1, h1, l1);
        hw[jw] = pack2(h0, h1);
        lw[jw] = pack2(l0, l1);
    }
    char* dst = ((W == 1) ? g_B1 : g_B2)
              + (((size_t)e * NT + nt) * KT + (yk * 2 + sub)) * BLKB;
    #pragma unroll
    for (int c = 0; c < 4; c++) {
        int ch = half * 4 + c;
        uint32_t off = (uint32_t)(n * 128) + (uint32_t)((ch ^ (n & 7)) << 4);
        *(uint4*)(dst + off)         = ((uint4*)hw)[c];
        *(uint4*)(dst + 16384 + off) = ((uint4*)lw)[c];
    }
}

// ---------------- warp-MMA grouped GEMM: BM=256, BN=128, BK=64, 2-stage ----------------
#define STAGE      98304u    // A: 2 blocks 64KB | B: 1 block 32KB
#define SM_TOKOFF  196608
#define SM_WVOFF   197632
#define SM_MBROFF  198656
#define SMEM_TOT   198720

template <int PHASE>
__global__ void __launch_bounds__(288, 1) moe_gemm(float* __restrict__ out) {
    constexpr int KT = (PHASE == 1) ? KT1 : KT2;
    const int tix = blockIdx.y;
    if (tix >= g_ntiles) return;
    const int e = g_tile_e[tix];
    const int gt = g_tile_gt[tix];
    const int nt = blockIdx.x;

    extern __shared__ char smem[];
    const uint32_t sb = s2u(smem);
    int* s_tok = (int*)(smem + SM_TOKOFF);
    float* s_wv = (float*)(smem + SM_WVOFF);
    const uint32_t mfull = sb + SM_MBROFF;        // 2 x 8B
    const uint32_t mempty = sb + SM_MBROFF + 16;  // 2 x 8B

    const int tid = threadIdx.x;
    const int wid = tid >> 5, lane = tid & 31;

    if (tid < 256) {
        int tk = g_ptok[gt * 256 + tid];
        s_tok[tid] = tk;
        s_wv[tid] = (tk >= 0) ? g_w[tk] : 0.f;
    }
    if (tid == 0) {
        #pragma unroll
        for (int i = 0; i < 2; i++) { mbar_init(mfull + i * 8, 1); mbar_init(mempty + i * 8, 8); }
    }
    __syncthreads();

    if (wid == 8) {
        if (lane == 0) {
            const char* srcA0 = ((PHASE == 1) ? g_A : g_H)
                              + (size_t)(gt * 2) * ((PHASE == 1) ? KT1 : KT2) * BLKB;
            const char* srcA1 = srcA0 + (size_t)KT * BLKB;
            const char* srcB = (PHASE == 1)
                ? (g_B1 + ((size_t)(e * NT1 + nt)) * KT1 * BLKB)
                : (g_B2 + ((size_t)(e * NT2 + nt)) * KT2 * BLKB);
            for (int kt = 0; kt < KT; kt++) {
                const int s = kt & 1;
                if (kt >= 2) mbar_wait(mempty + s * 8, ((kt - 2) >> 1) & 1);
                mbar_expect_tx(mfull + s * 8, STAGE);
                uint32_t d = sb + (uint32_t)s * STAGE;
                bulk_g2s(d,          srcA0 + (size_t)kt * BLKB, BLKB, mfull + s * 8);
                bulk_g2s(d + 32768u, srcA1 + (size_t)kt * BLKB, BLKB, mfull + s * 8);
                bulk_g2s(d + 65536u, srcB  + (size_t)kt * BLKB, BLKB, mfull + s * 8);
            }
        }
        return;
    }

    // consumer warps: wm in [0,4), wn in [0,2); warp tile 64M x 64N
    const int wm = wid >> 1, wn = wid & 1;
    const int lrA = (lane & 7) | (((lane >> 3) & 1) << 3);
    const int cA0 = lane >> 4;
    const int ars = lane & 7;
    uint32_t aBase[4];
    #pragma unroll
    for (int mf = 0; mf < 4; mf++) {
        int r = wm * 64 + mf * 16 + lrA;
        aBase[mf] = (uint32_t)((r >> 7) * 32768 + (r & 127) * 128);
    }
    const int lrB = (lane & 7) | ((lane >> 4) << 3);
    const int cB0 = (lane >> 3) & 1;
    const int brs = lane & 7;
    uint32_t bBase[2][2];
    #pragma unroll
    for (int pb = 0; pb < 2; pb++)
        #pragma unroll
        for (int q = 0; q < 2; q++)
            bBase[pb][q] = (uint32_t)((wn * 64 + pb * 32 + q * 16 + lrB) * 128);

    float acc[4][8][4];
    #pragma unroll
    for (int i = 0; i < 4; i++)
        #pragma unroll
        for (int j = 0; j < 8; j++)
            #pragma unroll
            for (int q = 0; q < 4; q++) acc[i][j][q] = 0.f;

    for (int kt = 0; kt < KT; kt++) {
        const int s = kt & 1;
        mbar_wait(mfull + s * 8, (kt >> 1) & 1);
        const uint32_t stA = sb + (uint32_t)s * STAGE;
        const uint32_t stB = stA + 65536u;
        #pragma unroll
        for (int ks = 0; ks < 4; ks++) {
            uint32_t ah[16], al[16];
            const uint32_t oA = (uint32_t)(((cA0 + ks * 2) ^ ars) << 4);
            #pragma unroll
            for (int mf = 0; mf < 4; mf++) {
                uint32_t ad = stA + aBase[mf] + oA;
                ldsm4(ah[mf*4], ah[mf*4+1], ah[mf*4+2], ah[mf*4+3], ad);
                ldsm4(al[mf*4], al[mf*4+1], al[mf*4+2], al[mf*4+3], ad + 16384u);
            }
            const uint32_t oB = (uint32_t)(((cB0 + ks * 2) ^ brs) << 4);
            #pragma unroll
            for (int pb = 0; pb < 2; pb++) {
                uint32_t bh[8], bl[8];
                #pragma unroll
                for (int q = 0; q < 2; q++) {
                    uint32_t bd = stB + bBase[pb][q] + oB;
                    ldsm4(bh[q*4], bh[q*4+1], bh[q*4+2], bh[q*4+3], bd);
                    ldsm4(bl[q*4], bl[q*4+1], bl[q*4+2], bl[q*4+3], bd + 16384u);
                }
                #pragma unroll
                for (int mf = 0; mf < 4; mf++)
                    #pragma unroll
                    for (int j = 0; j < 4; j++) {
                        float* c = acc[mf][pb * 4 + j];
                        const uint32_t* bhf = &bh[(j >> 1) * 4 + (j & 1) * 2];
                        const uint32_t* blf = &bl[(j >> 1) * 4 + (j & 1) * 2];
                        mma_bf16(c, &ah[mf * 4], bhf);
                        mma_bf16(c, &al[mf * 4], bhf);
                        mma_bf16(c, &ah[mf * 4], blf);
                    }
            }
        }
        if (lane == 0) mbar_arrive(mempty + s * 8);
    }

    // ---------------- epilogue ----------------
    #pragma unroll
    for (int mf = 0; mf < 4; mf++)
        #pragma unroll
        for (int nfi = 0; nfi < 8; nfi++) {
            const float* c = acc[mf][nfi];
            const int rbase = wm * 64 + mf * 16 + (lane >> 2);
            const int ncol = nt * 128 + wn * 64 + nfi * 8 + (lane & 3) * 2;
            #pragma unroll
            for (int hh = 0; hh < 2; hh++) {
                const int rl = rbase + hh * 8;
                if (PHASE == 1) {
                    if (s_tok[rl] < 0) continue;
                    float v0 = gelu_exact(c[hh * 2]);
                    float v1 = gelu_exact(c[hh * 2 + 1]);
                    float h0, l0, h1, l1;
                    split1(v0, h0, l0); split1(v1, h1, l1);
                    const int kt2 = ncol >> 6, kl = ncol & 63;
                    const int rb = rl & 127;
                    char* blk = g_H + ((size_t)(gt * 2 + (rl >> 7)) * KT2 + kt2) * BLKB;
                    uint32_t off = (uint32_t)(rb * 128)
                                 + (uint32_t)((((kl >> 3) ^ (rb & 7)) << 4) + (kl & 7) * 2);
                    *(uint32_t*)(blk + off)          = pack2(h0, h1);
                    *(uint32_t*)(blk + 16384u + off) = pack2(l0, l1);
                } else {
                    const int tk = s_tok[rl];
                    if (tk < 0) continue;
                    const float wv = s_wv[rl];
                    float2 o = make_float2(c[hh * 2] * wv, c[hh * 2 + 1] * wv);
                    *(float2*)(out + (size_t)tk * D_MODEL + ncol) = o;
                }
            }
        }
}

// ---------------- launch ----------------
extern "C" void kernel_launch(void* const* d_in, const int* in_sizes, int n_in,
                              void* d_out, int out_size) {
    const float* x  = (const float*)d_in[0];
    const float* Wr = (const float*)d_in[1];
    const float* W1 = (const float*)d_in[2];
    const float* W2 = (const float*)d_in[3];
    float* out = (float*)d_out;

    cudaFuncSetAttribute(moe_gemm<1>, cudaFuncAttributeMaxDynamicSharedMemorySize, SMEM_TOT);
    cudaFuncSetAttribute(moe_gemm<2>, cudaFuncAttributeMaxDynamicSharedMemorySize, SMEM_TOT);
    cudaFuncSetAttribute(transconv_kernel<1>,
                         cudaFuncAttributeMaxDynamicSharedMemorySize, 128 * 132 * 4);
    cudaFuncSetAttribute(transconv_kernel<2>,
                         cudaFuncAttributeMaxDynamicSharedMemorySize, 128 * 132 * 4);

    router_kernel<<<T_TOK, 256>>>(x, Wr);
    bucket_kernel<<<1, 1024>>>();
    gather_a_kernel<<<dim3(PM, KT1), 256>>>(x);
    transconv_kernel<1><<<dim3(NT1, D_MODEL / 128, NE), 512, 128 * 132 * 4>>>(W1);
    transconv_kernel<2><<<dim3(NT2, FF / 128, NE), 512, 128 * 132 * 4>>>(W2);
    moe_gemm<1><<<dim3(NT1, MAXTILE), 288, SMEM_TOT>>>(nullptr);
    moe_gemm<2><<<dim3(NT2, MAXTILE), 288, SMEM_TOT>>>(out);
}

// round 5
// speedup vs baseline: 1.3561x; 1.3561x over previous
#include <cuda_runtime.h>
#include <cuda_bf16.h>
#include <math.h>
#include <stdint.h>

#define T_TOK   4096
#define D_MODEL 2048
#define FF      8192
#define NE      8
#define PM      40          // padded 128-row blocks
#define MAXT    40          // max 128-row tiles
#define KT1     32          // GEMM1 k-tiles (D/64)
#define NT1     64          // GEMM1 n-tiles (FF/128)
#define KT2     128         // GEMM2 k-tiles (FF/64)
#define NT2     16          // GEMM2 n-tiles (D/128)
#define BLKB    32768       // operand block: hi 16KB + lo 16KB (128 rows x 128B)

// ---------------- scratch ----------------
__device__ int   g_idx[T_TOK];
__device__ float g_w[T_TOK];
__device__ int   g_order[T_TOK];
__device__ int   g_off[NE + 1];
__device__ int   g_ptok[PM * 128];
__device__ int   g_tile_e[MAXT];
__device__ int   g_tile_gt[MAXT];
__device__ int   g_tile_m64[MAXT];
__device__ int   g_ntiles;

__device__ __align__(128) char g_A [(size_t)PM * KT1 * BLKB];
__device__ __align__(128) char g_B1[(size_t)NE * NT1 * KT1 * BLKB];
__device__ __align__(128) char g_B2[(size_t)NE * NT2 * KT2 * BLKB];
__device__ __align__(128) char g_H [(size_t)PM * KT2 * BLKB];

// ---------------- helpers ----------------
__device__ __forceinline__ uint32_t s2u(const void* p) {
    uint32_t a;
    asm("{ .reg .u64 t; cvta.to.shared.u64 t, %1; cvt.u32.u64 %0, t; }" : "=r"(a) : "l"(p));
    return a;
}
__device__ __forceinline__ uint32_t pack2(float a, float b) {
    __nv_bfloat162 t = __floats2bfloat162_rn(a, b);
    return *(uint32_t*)&t;
}
__device__ __forceinline__ void split1(float v, float& hi, float& lo) {
    __nv_bfloat16 h = __float2bfloat16_rn(v);
    hi = __bfloat162float(h);
    lo = v - hi;
}
__device__ __forceinline__ float gelu_exact(float v) {
    return 0.5f * v * (1.0f + erff(v * 0.70710678118654752440f));
}
__device__ __forceinline__ void mbar_init(uint32_t m, uint32_t c) {
    asm volatile("mbarrier.init.shared::cta.b64 [%0], %1;" :: "r"(m), "r"(c) : "memory");
}
__device__ __forceinline__ void mbar_arrive(uint32_t m) {
    asm volatile("mbarrier.arrive.shared::cta.b64 _, [%0];" :: "r"(m) : "memory");
}
__device__ __forceinline__ void mbar_expect_tx(uint32_t m, uint32_t b) {
    asm volatile("mbarrier.arrive.expect_tx.shared::cta.b64 _, [%0], %1;"
                 :: "r"(m), "r"(b) : "memory");
}
__device__ __forceinline__ void mbar_wait(uint32_t m, uint32_t ph) {
    asm volatile(
        "{\n\t.reg .pred P;\n"
        "W_%=:\n\t"
        "mbarrier.try_wait.parity.acquire.cta.shared::cta.b64 P, [%0], %1, 0x989680;\n\t"
        "@P bra.uni D_%=;\n\t"
        "bra.uni W_%=;\n"
        "D_%=:\n\t}"
        :: "r"(m), "r"(ph) : "memory");
}
__device__ __forceinline__ void bulk_g2s(uint32_t dst, const void* src, uint32_t bytes,
                                         uint32_t mbar) {
    asm volatile(
        "cp.async.bulk.shared::cta.global.mbarrier::complete_tx::bytes [%0], [%1], %2, [%3];"
        :: "r"(dst), "l"(src), "r"(bytes), "r"(mbar) : "memory");
}
__device__ __forceinline__ void ldsm4(uint32_t& r0, uint32_t& r1, uint32_t& r2, uint32_t& r3,
                                      uint32_t a) {
    asm volatile("ldmatrix.sync.aligned.m8n8.x4.shared.b16 {%0,%1,%2,%3}, [%4];"
                 : "=r"(r0), "=r"(r1), "=r"(r2), "=r"(r3) : "r"(a));
}
__device__ __forceinline__ void mma_bf16(float* d, const uint32_t* a, const uint32_t* b) {
    asm volatile(
        "mma.sync.aligned.m16n8k16.row.col.f32.bf16.bf16.f32 "
        "{%0,%1,%2,%3}, {%4,%5,%6,%7}, {%8,%9}, {%0,%1,%2,%3};"
        : "+f"(d[0]), "+f"(d[1]), "+f"(d[2]), "+f"(d[3])
        : "r"(a[0]), "r"(a[1]), "r"(a[2]), "r"(a[3]), "r"(b[0]), "r"(b[1]));
}

// ---------------- router ----------------
__global__ void router_kernel(const float* __restrict__ x, const float* __restrict__ Wr) {
    __shared__ float sx[D_MODEL];
    __shared__ float slog[NE];
    const int t = blockIdx.x, tid = threadIdx.x;
    const float* xr = x + (size_t)t * D_MODEL;
    for (int i = tid * 4; i < D_MODEL; i += 256 * 4)
        *(float4*)(sx + i) = *(const float4*)(xr + i);
    __syncthreads();
    const int w = tid >> 5, lane = tid & 31;
    const float* wr = Wr + (size_t)w * D_MODEL;
    float s = 0.f;
    for (int i = lane; i < D_MODEL; i += 32) s += sx[i] * wr[i];
    #pragma unroll
    for (int o = 16; o; o >>= 1) s += __shfl_xor_sync(0xffffffffu, s, o);
    if (lane == 0) slog[w] = s;
    __syncthreads();
    if (tid == 0) {
        float mx = slog[0]; int mi = 0;
        #pragma unroll
        for (int e = 1; e < NE; e++) if (slog[e] > mx) { mx = slog[e]; mi = e; }
        float sum = 0.f;
        #pragma unroll
        for (int e = 0; e < NE; e++) sum += expf(slog[e] - mx);
        g_idx[t] = mi;
        g_w[t] = 1.0f / sum;
    }
}

// ---------------- bucket + tile table + padded token map ----------------
__global__ void bucket_kernel() {
    __shared__ int cnt[NE], off[NE], soff[NE], spo[NE + 1];
    const int tid = threadIdx.x;
    if (tid < NE) cnt[tid] = 0;
    __syncthreads();
    for (int t = tid; t < T_TOK; t += blockDim.x) atomicAdd(&cnt[g_idx[t]], 1);
    __syncthreads();
    if (tid == 0) {
        int acc = 0, pacc = 0, nt = 0;
        #pragma unroll
        for (int e = 0; e < NE; e++) {
            off[e] = acc; soff[e] = acc; g_off[e] = acc;
            spo[e] = pacc;
            int tiles = (cnt[e] + 127) >> 7;
            for (int i = 0; i < tiles; i++) {
                g_tile_e[nt] = e;
                g_tile_gt[nt] = (pacc >> 7) + i;
                g_tile_m64[nt] = (cnt[e] - i * 128) <= 64;
                nt++;
            }
            acc += cnt[e];
            pacc += tiles << 7;
        }
        g_off[NE] = acc;
        spo[NE] = pacc;
        g_ntiles = nt;
    }
    __syncthreads();
    for (int t = tid; t < T_TOK; t += blockDim.x) {
        int p = atomicAdd(&off[g_idx[t]], 1);
        g_order[p] = t;
    }
    __syncthreads();
    for (int p = tid; p < PM * 128; p += blockDim.x) {
        int tk = -1;
        #pragma unroll
        for (int e = 0; e < NE; e++)
            if (p >= spo[e] && p < spo[e] + cnt[e])
                tk = g_order[soff[e] + (p - spo[e])];
        g_ptok[p] = tk;
    }
}

// ---------------- prepass: gather x rows -> swizzled bf16 hi/lo blocks ----------------
__global__ void __launch_bounds__(256) gather_a_kernel(const float* __restrict__ x) {
    const int gt = blockIdx.x, kt = blockIdx.y;
    const int tid = threadIdx.x;
    const int r = tid >> 1, half = tid & 1;
    const int tok = g_ptok[gt * 128 + r];
    uint32_t hw[16], lw[16];
    if (tok >= 0) {
        const float4* src = (const float4*)(x + (size_t)tok * D_MODEL + kt * 64 + half * 32);
        #pragma unroll
        for (int q = 0; q < 8; q++) {
            float4 v = src[q];
            float h0, l0, h1, l1, h2, l2, h3, l3;
            split1(v.x, h0, l0); split1(v.y, h1, l1);
            split1(v.z, h2, l2); split1(v.w, h3, l3);
            hw[q * 2]     = pack2(h0, h1); hw[q * 2 + 1] = pack2(h2, h3);
            lw[q * 2]     = pack2(l0, l1); lw[q * 2 + 1] = pack2(l2, l3);
        }
    } else {
        #pragma unroll
        for (int q = 0; q < 16; q++) { hw[q] = 0; lw[q] = 0; }
    }
    char* blk = g_A + ((size_t)gt * KT1 + kt) * BLKB;
    #pragma unroll
    for (int c = 0; c < 4; c++) {
        int ch = half * 4 + c;
        uint32_t off = (uint32_t)(r * 128) + (uint32_t)((ch ^ (r & 7)) << 4);
        *(uint4*)(blk + off)         = ((uint4*)hw)[c];
        *(uint4*)(blk + 16384 + off) = ((uint4*)lw)[c];
    }
}

// ---------------- prepass: transpose + convert weights (R3 config) ----------------
template <int W>
__global__ void __launch_bounds__(256) transconv_kernel(const float* __restrict__ src) {
    constexpr int Cn = (W == 1) ? FF : D_MODEL;
    constexpr int Rk = (W == 1) ? D_MODEL : FF;
    constexpr int NT = (W == 1) ? NT1 : NT2;
    constexpr int KT = (W == 1) ? KT1 : KT2;
    __shared__ float s[64 * 132];
    const int nt = blockIdx.x, kt = blockIdx.y, e = blockIdx.z;
    const int tid = threadIdx.x;
    const float* sp = src + (size_t)e * Rk * Cn + (size_t)(kt * 64) * Cn + nt * 128;
    #pragma unroll
    for (int i = 0; i < 8; i++) {
        int q = i * 256 + tid;
        int k = q >> 5, c4 = q & 31;
        *(float4*)(s + k * 132 + c4 * 4) = *(const float4*)(sp + (size_t)k * Cn + c4 * 4);
    }
    __syncthreads();
    const int n = tid >> 1, half = tid & 1;
    uint32_t hw[16], lw[16];
    #pragma unroll
    for (int jw = 0; jw < 16; jw++) {
        float v0 = s[(half * 32 + jw * 2) * 132 + n];
        float v1 = s[(half * 32 + jw * 2 + 1) * 132 + n];
        float h0, l0, h1, l1;
        split1(v0, h0, l0); split1(v1, h1, l1);
        hw[jw] = pack2(h0, h1);
        lw[jw] = pack2(l0, l1);
    }
    char* dst = ((W == 1) ? g_B1 : g_B2) + (((size_t)e * NT + nt) * KT + kt) * BLKB;
    #pragma unroll
    for (int c = 0; c < 4; c++) {
        int ch = half * 4 + c;
        uint32_t off = (uint32_t)(n * 128) + (uint32_t)((ch ^ (n & 7)) << 4);
        *(uint4*)(dst + off)         = ((uint4*)hw)[c];
        *(uint4*)(dst + 16384 + off) = ((uint4*)lw)[c];
    }
}

// ---------------- warp-MMA grouped GEMM (R3 config + m64 skip + 3-pass) --------------
#define ST_BYTES   65536u
#define SM_TOKOFF  196608
#define SM_WVOFF   197120
#define SM_MBROFF  197632
#define SMEM_TOT   197696

template <int PHASE>
__global__ void __launch_bounds__(288, 1) moe_gemm(float* __restrict__ out) {
    constexpr int KT = (PHASE == 1) ? KT1 : KT2;
    const int tix = blockIdx.y;
    if (tix >= g_ntiles) return;
    const int e = g_tile_e[tix];
    const int gt = g_tile_gt[tix];
    const int m64 = g_tile_m64[tix];
    const int nt = blockIdx.x;

    extern __shared__ char smem[];
    const uint32_t sb = s2u(smem);
    int* s_tok = (int*)(smem + SM_TOKOFF);
    float* s_wv = (float*)(smem + SM_WVOFF);
    const uint32_t mfull = sb + SM_MBROFF;
    const uint32_t mempty = sb + SM_MBROFF + 24;

    const int tid = threadIdx.x;
    const int wid = tid >> 5, lane = tid & 31;

    if (tid < 128) {
        int tk = g_ptok[gt * 128 + tid];
        s_tok[tid] = tk;
        s_wv[tid] = (tk >= 0) ? g_w[tk] : 0.f;
    }
    if (tid == 0) {
        #pragma unroll
        for (int i = 0; i < 3; i++) { mbar_init(mfull + i * 8, 1); mbar_init(mempty + i * 8, 8); }
    }
    __syncthreads();

    if (wid == 8) {
        if (lane == 0) {
            const char* srcA = (PHASE == 1) ? (g_A + (size_t)gt * KT1 * BLKB)
                                            : (g_H + (size_t)gt * KT2 * BLKB);
            const char* srcB = (PHASE == 1)
                ? (g_B1 + ((size_t)(e * NT1 + nt)) * KT1 * BLKB)
                : (g_B2 + ((size_t)(e * NT2 + nt)) * KT2 * BLKB);
            int s = 0, r = 0;
            for (int kt = 0; kt < KT; kt++) {
                if (r > 0) mbar_wait(mempty + s * 8, (r - 1) & 1);
                mbar_expect_tx(mfull + s * 8, ST_BYTES);
                uint32_t dst = sb + (uint32_t)s * ST_BYTES;
                bulk_g2s(dst,          srcA + (size_t)kt * BLKB, BLKB, mfull + s * 8);
                bulk_g2s(dst + 32768u, srcB + (size_t)kt * BLKB, BLKB, mfull + s * 8);
                if (++s == 3) { s = 0; r++; }
            }
        }
        return;
    }

    // consumer warps: wm in [0,2) (64 M-rows each), wn in [0,4) (32 N-cols each)
    const int wm = wid >> 2, wn = wid & 3;
    const bool skipw = (m64 && wm == 1);

    const int lrA = (lane & 7) + ((lane >> 3) & 1) * 8;
    const int cA0 = lane >> 4;
    uint32_t a_off[4]; int a_rs[4];
    #pragma unroll
    for (int mf = 0; mf < 4; mf++) {
        int rr = wm * 64 + mf * 16 + lrA;
        a_off[mf] = (uint32_t)(rr * 128);
        a_rs[mf] = rr & 7;
    }
    const int lrB = (lane & 7) + ((lane >> 4) << 3);
    const int cB0 = (lane >> 3) & 1;
    uint32_t b_off[2]; int b_rs[2];
    #pragma unroll
    for (int p = 0; p < 2; p++) {
        int rr = wn * 32 + p * 16 + lrB;
        b_off[p] = (uint32_t)(rr * 128);
        b_rs[p] = rr & 7;
    }

    float acc[4][4][4];
    #pragma unroll
    for (int i = 0; i < 4; i++)
        #pragma unroll
        for (int j = 0; j < 4; j++)
            #pragma unroll
            for (int q = 0; q < 4; q++) acc[i][j][q] = 0.f;

    int s = 0, r = 0;
    for (int kt = 0; kt < KT; kt++) {
        mbar_wait(mfull + s * 8, r & 1);
        if (!skipw) {
            const uint32_t stA = sb + (uint32_t)s * ST_BYTES;
            const uint32_t stB = stA + 32768u;
            #pragma unroll
            for (int ks = 0; ks < 4; ks++) {
                uint32_t ah[16], al[16], bh[8], bl[8];
                const int cA = cA0 + ks * 2;
                #pragma unroll
                for (int mf = 0; mf < 4; mf++) {
                    uint32_t o = a_off[mf] + (uint32_t)((cA ^ a_rs[mf]) << 4);
                    ldsm4(ah[mf*4], ah[mf*4+1], ah[mf*4+2], ah[mf*4+3], stA + o);
                    ldsm4(al[mf*4], al[mf*4+1], al[mf*4+2], al[mf*4+3], stA + 16384u + o);
                }
                const int cB = cB0 + ks * 2;
                #pragma unroll
                for (int p = 0; p < 2; p++) {
                    uint32_t o = b_off[p] + (uint32_t)((cB ^ b_rs[p]) << 4);
                    ldsm4(bh[p*4], bh[p*4+1], bh[p*4+2], bh[p*4+3], stB + o);
                    ldsm4(bl[p*4], bl[p*4+1], bl[p*4+2], bl[p*4+3], stB + 16384u + o);
                }
                // pass 1: hi * hi  (16 independent MMAs)
                #pragma unroll
                for (int mf = 0; mf < 4; mf++)
                    #pragma unroll
                    for (int nf = 0; nf < 4; nf++)
                        mma_bf16(acc[mf][nf], &ah[mf * 4], &bh[(nf >> 1) * 4 + (nf & 1) * 2]);
                // pass 2: lo_a * hi_b
                #pragma unroll
                for (int mf = 0; mf < 4; mf++)
                    #pragma unroll
                    for (int nf = 0; nf < 4; nf++)
                        mma_bf16(acc[mf][nf], &al[mf * 4], &bh[(nf >> 1) * 4 + (nf & 1) * 2]);
                // pass 3: hi_a * lo_b
                #pragma unroll
                for (int mf = 0; mf < 4; mf++)
                    #pragma unroll
                    for (int nf = 0; nf < 4; nf++)
                        mma_bf16(acc[mf][nf], &ah[mf * 4], &bl[(nf >> 1) * 4 + (nf & 1) * 2]);
            }
        }
        if (lane == 0) mbar_arrive(mempty + s * 8);
        if (++s == 3) { s = 0; r++; }
    }

    if (skipw) return;

    // ---------------- epilogue ----------------
    #pragma unroll
    for (int mf = 0; mf < 4; mf++)
        #pragma unroll
        for (int nf = 0; nf < 4; nf++) {
            const float* c = acc[mf][nf];
            const int rbase = wm * 64 + mf * 16 + (lane >> 2);
            const int ncol = nt * 128 + wn * 32 + nf * 8 + (lane & 3) * 2;
            #pragma unroll
            for (int hh = 0; hh < 2; hh++) {
                const int rl = rbase + hh * 8;
                if (PHASE == 1) {
                    if (s_tok[rl] < 0) continue;
                    float v0 = gelu_exact(c[hh * 2]);
                    float v1 = gelu_exact(c[hh * 2 + 1]);
                    float h0, l0, h1, l1;
                    split1(v0, h0, l0); split1(v1, h1, l1);
                    const int kt2 = ncol >> 6, kl = ncol & 63;
                    char* blk = g_H + ((size_t)gt * KT2 + kt2) * BLKB;
                    uint32_t off = (uint32_t)(rl * 128)
                                 + (uint32_t)((((kl >> 3) ^ (rl & 7)) << 4) + (kl & 7) * 2);
                    *(uint32_t*)(blk + off)          = pack2(h0, h1);
                    *(uint32_t*)(blk + 16384u + off) = pack2(l0, l1);
                } else {
                    const int tk = s_tok[rl];
                    if (tk < 0) continue;
                    const float wv = s_wv[rl];
                    float2 o = make_float2(c[hh * 2] * wv, c[hh * 2 + 1] * wv);
                    *(float2*)(out + (size_t)tk * D_MODEL + ncol) = o;
                }
            }
        }
}

// ---------------- launch ----------------
extern "C" void kernel_launch(void* const* d_in, const int* in_sizes, int n_in,
                              void* d_out, int out_size) {
    const float* x  = (const float*)d_in[0];
    const float* Wr = (const float*)d_in[1];
    const float* W1 = (const float*)d_in[2];
    const float* W2 = (const float*)d_in[3];
    float* out = (float*)d_out;

    cudaFuncSetAttribute(moe_gemm<1>, cudaFuncAttributeMaxDynamicSharedMemorySize, SMEM_TOT);
    cudaFuncSetAttribute(moe_gemm<2>, cudaFuncAttributeMaxDynamicSharedMemorySize, SMEM_TOT);

    router_kernel<<<T_TOK, 256>>>(x, Wr);
    bucket_kernel<<<1, 1024>>>();
    gather_a_kernel<<<dim3(PM, KT1), 256>>>(x);
    transconv_kernel<1><<<dim3(NT1, KT1, NE), 256>>>(W1);
    transconv_kernel<2><<<dim3(NT2, KT2, NE), 256>>>(W2);
    moe_gemm<1><<<dim3(NT1, MAXT), 288, SMEM_TOT>>>(nullptr);
    moe_gemm<2><<<dim3(NT2, MAXT), 288, SMEM_TOT>>>(out);
}